// round 14
// baseline (speedup 1.0000x reference)
#include <cuda_runtime.h>
#include <cuda_fp16.h>
#include <math.h>
#include <stdint.h>

#define BATCH 2
#define SEQ   2048
#define HID   2048
#define NH    16
#define DNOPE 128
#define DROPE 64
#define DV    128
#define DQK   192
#define LORA  512
#define ROWS  (BATCH*SEQ)   // 4096
#define NS    5             // cp.async pipeline stages (single-sync design)

// ---------------- scratch (static device memory; no allocations) ----------------
__device__ __half g_hidden16[(size_t)ROWS*HID];
__device__ __half g_wqd16 [(size_t)1536*HID];
__device__ __half g_wqup16[(size_t)3072*1536];
__device__ __half g_wkvd16[(size_t)576*HID];
__device__ __half g_wkvup16[(size_t)4096*512];
__device__ __half g_wout16[(size_t)HID*HID];
__device__ __half g_qtmp16[(size_t)ROWS*1536];
__device__ __half g_qbig16[(size_t)ROWS*3072];
__device__ __half g_c16   [(size_t)ROWS*576];
__device__ __half g_kv16  [(size_t)ROWS*4096];
__device__ __half g_Q16   [(size_t)BATCH*NH*SEQ*DQK];
__device__ __half g_K16   [(size_t)BATCH*NH*SEQ*DQK];
__device__ __half g_Vt16  [(size_t)BATCH*NH*DV*SEQ];   // V transposed per (b,h)
__device__ __half g_ctx16 [(size_t)ROWS*NH*DV];
__device__ __half g_attn16[(size_t)BATCH*NH*SEQ*SEQ];  // fp16 attn for attn@V
__device__ float  g_attn_fb[(size_t)BATCH*NH*SEQ*SEQ]; // fallback fp32 attn

__device__ __forceinline__ uint32_t smem_u32(const void* p) {
    uint32_t a;
    asm("{ .reg .u64 t; cvta.to.shared.u64 t, %1; cvt.u32.u64 %0, t; }" : "=r"(a) : "l"(p));
    return a;
}

#define MMA_F16(ac, ar, br)                                                       \
    asm volatile("mma.sync.aligned.m16n8k16.row.col.f32.f16.f16.f32 "             \
                 "{%0,%1,%2,%3}, {%4,%5,%6,%7}, {%8,%9}, {%0,%1,%2,%3};"          \
                 : "+f"((ac)[0]), "+f"((ac)[1]), "+f"((ac)[2]), "+f"((ac)[3])     \
                 : "r"((ar)[0]), "r"((ar)[1]), "r"((ar)[2]), "r"((ar)[3]),        \
                   "r"((br)[0]), "r"((br)[1]))

#define LDSM_X4(r0, r1, r2, r3, addr)                                             \
    asm volatile("ldmatrix.sync.aligned.m8n8.x4.shared.b16 {%0,%1,%2,%3}, [%4];"  \
                 : "=r"(r0), "=r"(r1), "=r"(r2), "=r"(r3) : "r"(addr))

// ---------------- fp32 -> fp16 conversion ----------------
__global__ __launch_bounds__(256) void f2h_kernel(
    const float4* __restrict__ src, uint2* __restrict__ dst, int n4)
{
    int i = blockIdx.x * blockDim.x + threadIdx.x;
    if (i < n4) {
        float4 v = src[i];
        __half2 a = __floats2half2_rn(v.x, v.y);
        __half2 b = __floats2half2_rn(v.z, v.w);
        dst[i] = make_uint2(*(uint32_t*)&a, *(uint32_t*)&b);
    }
}

// ---------------- zero the masked fp32 attn tail (runs early, overlapped) -------
__global__ __launch_bounds__(256) void zero_tail(float* __restrict__ attn)
{
    long long r = blockIdx.x;
    int q = (int)(r % SEQ);
    int len16 = ((q + 1) + 127) & ~127;
    float4* row = (float4*)(attn + r * SEQ);
    float4 z4 = make_float4(0.f, 0.f, 0.f, 0.f);
    for (int i = (len16 >> 2) + threadIdx.x; i < SEQ / 4; i += 256)
        row[i] = z4;
}

// ---------------- fp16 mma.sync NT GEMM: cp.async.cg(16B) + ldmatrix.x4 ---------
// C[m,n] = alpha * sum_k A[m,k]*B[n,k] ; fp16 gmem, fp32 accumulate.
// CTA 128 x (NI*32), BK=32, 8 warps (warp 64 x NI*8), MINB CTAs/SM.
// NI=4: 2 CTA/SM (proven R8 config). NI=8: 1 CTA/SM, half the per-flop
// fragment/sync overhead for large-N GEMMs.
// SMEM: row = 32 halves (64B) = 4 x 16B units, unit swizzle u^((row>>1)&3).
// mode: 0 dense; 1 causal tile-skip (n0 > m0) + epilogue clamps cols >= m0+128
// to 0.0f (256-wide tiles overhang the mask); 2 causal K-trunc, heavy-first.
// Merged-output: tiles with n0 >= Nsplit switch to B2/C2/N2/ldc2.
template<int NI, int MINB>
__global__ __launch_bounds__(256, MINB) void gemm_h16(
    const __half* __restrict__ A, const __half* __restrict__ B, void* __restrict__ Cv,
    int M, int N, int K, int lda, int ldb, int ldc,
    int zdiv, long long sA1, long long sA2,
    long long sB1, long long sB2, long long sC1, long long sC2,
    float alpha, int mode, int outhalf,
    const __half* __restrict__ B2, void* __restrict__ C2,
    int Nsplit, int N2, int ldc2)
{
    constexpr int BN      = NI * 32;           // CTA N width
    constexpr int BBYTES  = BN * 64;           // B bytes per stage
    constexpr int STAGEB  = 8192 + BBYTES;     // stage size

    int z  = blockIdx.z;
    int my = (mode == 2) ? (gridDim.y - 1 - blockIdx.y) : blockIdx.y;  // heavy-first
    int m0 = my * 128;
    int n0 = blockIdx.x * BN;
    if (mode == 1 && n0 > m0) return;   // masked tile: tail zeroed by zero_tail

    const __half* Ab = A + (long long)(z / zdiv) * sA1 + (long long)(z % zdiv) * sA2;
    const __half* Bb = B + (long long)(z / zdiv) * sB1 + (long long)(z % zdiv) * sB2;
    long long coff = (long long)(z / zdiv) * sC1 + (long long)(z % zdiv) * sC2;

    if (Nsplit > 0 && n0 >= Nsplit) {   // merged second output region
        Bb = B2; n0 -= Nsplit; N = N2; Cv = C2; ldc = ldc2; coff = 0;
    }

    extern __shared__ uint32_t sm[];
    uint32_t smb = smem_u32(sm);

    int t    = threadIdx.x;
    int lane = t & 31;
    int wid  = t >> 5;
    int g    = lane >> 2;
    int t4   = lane & 3;
    int wm   = wid >> 2;        // 0..1
    int wn   = wid & 3;         // 0..3

    int kEnd = K;
    if (mode == 2) { int ke = m0 + 128; kEnd = (ke < K) ? ke : K; }
    int nk = kEnd >> 5;

    float acc[4][NI][4];
    #pragma unroll
    for (int mi = 0; mi < 4; mi++)
        #pragma unroll
        for (int ni = 0; ni < NI; ni++)
            #pragma unroll
            for (int r = 0; r < 4; r++) acc[mi][ni][r] = 0.0f;

    // ---- staging geometry: thread t covers 16B unit (row = t>>2 + 64*i, u = t&3)
    int urow = t >> 2;            // 0..63
    int uu   = t & 3;
    int sxu  = uu ^ ((urow >> 1) & 3);   // swizzled unit (invariant under row+=64)

    auto issue = [&](int kt, int st) {
        int k0 = kt << 5;
        uint32_t sA = smb + st * STAGEB;
        uint32_t sB = sA + 8192;
        #pragma unroll
        for (int i = 0; i < 2; i++) {
            int row = urow + i * 64;
            uint32_t dst = (uint32_t)(row * 64 + (sxu << 4));
            const __half* ga = Ab + (size_t)(m0 + row) * lda + k0 + uu * 8;
            asm volatile("cp.async.cg.shared.global [%0], [%1], 16;"
                         :: "r"(sA + dst), "l"(ga));
        }
        #pragma unroll
        for (int i = 0; i < NI / 2; i++) {
            int row = urow + i * 64;
            uint32_t dst = (uint32_t)(row * 64 + (sxu << 4));
            int brow = n0 + row;
            const __half* gb = Bb + (size_t)(brow < N ? brow : 0) * ldb + k0 + uu * 8;
            int ssz = (brow < N) ? 16 : 0;
            asm volatile("cp.async.cg.shared.global [%0], [%1], 16, %2;"
                         :: "r"(sB + dst), "l"(gb), "r"(ssz));
        }
    };

    // ---- ldmatrix per-lane address components
    int m_idx = lane >> 3;        // matrix index 0..3
    int rin   = lane & 7;
    int arow0 = wm * 64 + rin + (m_idx & 1) * 8;
    int aun   = m_idx >> 1;                   // 0=klo,1=khi
    int axs   = (arow0 >> 1) & 3;
    uint32_t aoffb = (uint32_t)(arow0 * 64);
    int brow0 = wn * (NI * 8) + rin + (m_idx >> 1) * 8;
    int bun   = m_idx & 1;
    int bxs   = (brow0 >> 1) & 3;
    uint32_t boffb = (uint32_t)(brow0 * 64);

    auto mma_chunk = [&](int st) {
        uint32_t sA = smb + st * STAGEB;
        uint32_t sB = sA + 8192;
        #pragma unroll
        for (int ks = 0; ks < 2; ks++) {
            uint32_t af[4][4], bf[NI][2];
            uint32_t au = (uint32_t)(((2 * ks + aun) ^ axs) << 4);
            uint32_t bu = (uint32_t)(((2 * ks + bun) ^ bxs) << 4);
            #pragma unroll
            for (int mi = 0; mi < 4; mi++)
                LDSM_X4(af[mi][0], af[mi][1], af[mi][2], af[mi][3],
                        sA + aoffb + (uint32_t)(mi * 1024) + au);
            #pragma unroll
            for (int p = 0; p < NI / 2; p++)
                LDSM_X4(bf[2*p][0], bf[2*p][1], bf[2*p+1][0], bf[2*p+1][1],
                        sB + boffb + (uint32_t)(p * 1024) + bu);
            #pragma unroll
            for (int mi = 0; mi < 4; mi++)
                #pragma unroll
                for (int ni = 0; ni < NI; ni++)
                    MMA_F16(acc[mi][ni], af[mi], bf[ni]);
        }
    };

    // prologue
    #pragma unroll
    for (int s = 0; s < NS - 1; s++) {
        if (s < nk) issue(s, s);
        asm volatile("cp.async.commit_group;" ::: "memory");
    }

    int st = 0, stw = NS - 1;
    for (int kt = 0; kt < nk; kt++) {
        asm volatile("cp.async.wait_group %0;" :: "n"(NS - 2) : "memory");
        __syncthreads();
        mma_chunk(st);
        int nxt = kt + NS - 1;
        if (nxt < nk) issue(nxt, stw);
        asm volatile("cp.async.commit_group;" ::: "memory");
        if (++st == NS) st = 0;
        if (++stw == NS) stw = 0;
    }

    // epilogue
    int mclamp = m0 + 128;   // mode 1: cols >= m0+128 are masked -> write 0
    #pragma unroll
    for (int mi = 0; mi < 4; mi++) {
        int row = m0 + wm * 64 + mi * 16 + g;
        #pragma unroll
        for (int ni = 0; ni < NI; ni++) {
            int col = n0 + wn * (NI * 8) + ni * 8 + 2 * t4;
            if (col < N) {
                if (outhalf) {
                    __half* Cb = (__half*)Cv + coff;
                    __half2 h0 = __floats2half2_rn(alpha * acc[mi][ni][0], alpha * acc[mi][ni][1]);
                    __half2 h1 = __floats2half2_rn(alpha * acc[mi][ni][2], alpha * acc[mi][ni][3]);
                    *(__half2*)(Cb + (size_t)row * ldc + col)       = h0;
                    *(__half2*)(Cb + (size_t)(row + 8) * ldc + col) = h1;
                } else {
                    float* Cb = (float*)Cv + coff;
                    bool zz = (mode == 1) && (col >= mclamp);
                    float2 v0, v1;
                    if (zz) { v0 = make_float2(0.f, 0.f); v1 = v0; }
                    else {
                        v0 = make_float2(alpha * acc[mi][ni][0], alpha * acc[mi][ni][1]);
                        v1 = make_float2(alpha * acc[mi][ni][2], alpha * acc[mi][ni][3]);
                    }
                    *(float2*)(Cb + (size_t)row * ldc + col)       = v0;
                    *(float2*)(Cb + (size_t)(row + 8) * ldc + col) = v1;
                }
            }
        }
    }
}

// ---------------- block reductions ----------------
__device__ __forceinline__ float blockReduceSum(float v) {
    __shared__ float sh[32];
    int lane = threadIdx.x & 31, w = threadIdx.x >> 5;
    #pragma unroll
    for (int o = 16; o > 0; o >>= 1) v += __shfl_xor_sync(0xffffffffu, v, o);
    __syncthreads();
    if (lane == 0) sh[w] = v;
    __syncthreads();
    int nw = (blockDim.x + 31) >> 5;
    float r = (threadIdx.x < nw) ? sh[threadIdx.x] : 0.0f;
    if (w == 0) {
        #pragma unroll
        for (int o = 16; o > 0; o >>= 1) r += __shfl_xor_sync(0xffffffffu, r, o);
        if (lane == 0) sh[0] = r;
    }
    __syncthreads();
    return sh[0];
}
__device__ __forceinline__ float blockReduceMax(float v) {
    __shared__ float sh[32];
    int lane = threadIdx.x & 31, w = threadIdx.x >> 5;
    #pragma unroll
    for (int o = 16; o > 0; o >>= 1) v = fmaxf(v, __shfl_xor_sync(0xffffffffu, v, o));
    __syncthreads();
    if (lane == 0) sh[w] = v;
    __syncthreads();
    int nw = (blockDim.x + 31) >> 5;
    float r = (threadIdx.x < nw) ? sh[threadIdx.x] : -INFINITY;
    if (w == 0) {
        #pragma unroll
        for (int o = 16; o > 0; o >>= 1) r = fmaxf(r, __shfl_xor_sync(0xffffffffu, r, o));
        if (lane == 0) sh[0] = r;
    }
    __syncthreads();
    return sh[0];
}

// ---------------- RMSNorm fp16 (in place) ----------------
__global__ __launch_bounds__(256) void rmsnorm16(
    __half* __restrict__ x, const float* __restrict__ w, int W, int stride)
{
    __half* row = x + (long long)blockIdx.x * stride;
    float ss = 0.0f;
    for (int i = threadIdx.x; i < W; i += blockDim.x) {
        float v = __half2float(row[i]); ss += v * v;
    }
    ss = blockReduceSum(ss);
    float sc = rsqrtf(ss / (float)W + 1e-6f);
    for (int i = threadIdx.x; i < W; i += blockDim.x)
        row[i] = __float2half(__half2float(row[i]) * sc * w[i]);
}

// ---------------- RoPE + pack fp16 (Q, K only) ----------------
__global__ __launch_bounds__(256) void rope_pack16(
    const __half* __restrict__ q,   // [ROWS,3072]
    const __half* __restrict__ c,   // [ROWS,576]
    const __half* __restrict__ kv,  // [ROWS,4096]
    __half* __restrict__ Qo,        // [B,NH,S,192]
    __half* __restrict__ Ko)        // [B,NH,S,192]
{
    int row = blockIdx.x;
    int b = row / SEQ, s = row % SEQ;
    int t = threadIdx.x;

    __shared__ float cs[32], sn[32];
    __shared__ __half kr[64];
    if (t < 32) {
        float f = exp10f(-(float)t / 8.0f);   // 10000^(-t/32)
        float ang = (float)s * f;
        sincosf(ang, &sn[t], &cs[t]);
    }
    __syncthreads();
    if (t < 64) {
        const __half* kx = c + (long long)row * 576 + 512;
        int j = t; float v;
        if (j < 32) v = __half2float(kx[2*j]) * cs[j] - __half2float(kx[2*j+1]) * sn[j];
        else { int i = j - 32; v = __half2float(kx[2*i+1]) * cs[i] + __half2float(kx[2*i]) * sn[i]; }
        kr[j] = __float2half(v);
    }
    __syncthreads();

    const __half* qrow = q + (long long)row * 3072;
    for (int idx = t; idx < NH * DQK; idx += 256) {
        int h = idx / DQK, d = idx % DQK;
        __half v;
        if (d < DNOPE) v = qrow[h * DQK + d];
        else {
            int j = d - DNOPE;
            const __half* qx = qrow + h * DQK + DNOPE;
            float vv;
            if (j < 32) vv = __half2float(qx[2*j]) * cs[j] - __half2float(qx[2*j+1]) * sn[j];
            else { int i = j - 32; vv = __half2float(qx[2*i+1]) * cs[i] + __half2float(qx[2*i]) * sn[i]; }
            v = __float2half(vv);
        }
        Qo[((long long)(b * NH + h) * SEQ + s) * DQK + d] = v;
    }

    const __half* kvrow = kv + (long long)row * 4096;
    for (int idx = t; idx < NH * DQK; idx += 256) {
        int h = idx / DQK, d = idx % DQK;
        __half v = (d < DNOPE) ? kvrow[h * 256 + d] : kr[d - DNOPE];
        Ko[((long long)(b * NH + h) * SEQ + s) * DQK + d] = v;
    }
}

// ---------------- V transpose: kv16[b,s,h,256](+128) -> Vt[bh, d, s] ------------
__global__ __launch_bounds__(256) void vtrans(
    const __half* __restrict__ kv, __half* __restrict__ Vt)
{
    __shared__ __half tile[64][33];
    int s0 = blockIdx.x * 64;
    int d0 = blockIdx.y * 32;
    int z  = blockIdx.z;           // b*NH + h
    int b = z / NH, h = z % NH;
    int tx = threadIdx.x & 31;
    int ty = threadIdx.x >> 5;     // 0..7
    const __half* src = kv + (size_t)b * SEQ * 4096 + h * 256 + 128 + d0;
    #pragma unroll
    for (int k = 0; k < 8; k++) {
        int row = ty * 8 + k;
        tile[row][tx] = src[(size_t)(s0 + row) * 4096 + tx];
    }
    __syncthreads();
    #pragma unroll
    for (int k = 0; k < 4; k++) {
        int d = ty + 8 * k;
        __half2 v = __halves2half2(tile[2 * tx][d], tile[2 * tx + 1][d]);
        *(__half2*)&Vt[((size_t)z * DV + d0 + d) * SEQ + s0 + 2 * tx] = v;
    }
}

// ---------------- causal softmax: fp32 writes trimmed to the diagonal block -----
__global__ __launch_bounds__(256) void softmax_causal(
    float* __restrict__ attn, __half* __restrict__ attn16)
{
    long long r = blockIdx.x;
    int q = (int)(r % SEQ);
    float4* row4   = (float4*)(attn + r * SEQ);
    uint2*  row16  = (uint2*)(attn16 + r * SEQ);
    int t = threadIdx.x;
    int len = q + 1;
    int len16 = (len + 127) & ~127;

    float4 v[2];
    float mx = -INFINITY;
    #pragma unroll
    for (int it = 0; it < 2; it++) {
        int i4 = t + it * 256;
        int base = i4 * 4;
        float4 x = make_float4(-INFINITY, -INFINITY, -INFINITY, -INFINITY);
        if (base < len) {
            x = row4[i4];
            if (base + 1 >= len) x.y = -INFINITY;
            if (base + 2 >= len) x.z = -INFINITY;
            if (base + 3 >= len) x.w = -INFINITY;
        }
        v[it] = x;
        mx = fmaxf(mx, fmaxf(fmaxf(x.x, x.y), fmaxf(x.z, x.w)));
    }
    mx = blockReduceMax(mx);

    float sum = 0.0f;
    #pragma unroll
    for (int it = 0; it < 2; it++) {
        float4 x = v[it];
        x.x = (x.x == -INFINITY) ? 0.0f : __expf(x.x - mx);
        x.y = (x.y == -INFINITY) ? 0.0f : __expf(x.y - mx);
        x.z = (x.z == -INFINITY) ? 0.0f : __expf(x.z - mx);
        x.w = (x.w == -INFINITY) ? 0.0f : __expf(x.w - mx);
        v[it] = x;
        sum += x.x + x.y + x.z + x.w;
    }
    sum = blockReduceSum(sum);
    float inv = 1.0f / sum;

    #pragma unroll
    for (int it = 0; it < 2; it++) {
        int i4 = t + it * 256;
        int base = i4 * 4;
        if (base < len16) {
            float4 x = v[it];
            x.x *= inv; x.y *= inv; x.z *= inv; x.w *= inv;
            row4[i4] = x;
            __half2 a = __floats2half2_rn(x.x, x.y);
            __half2 b = __floats2half2_rn(x.z, x.w);
            row16[i4] = make_uint2(*(uint32_t*)&a, *(uint32_t*)&b);
        }
    }
}

// ---------------- streams/events for graph-capture fork/join --------------------
static cudaStream_t g_s1 = 0;
static cudaEvent_t  g_ev[5];
static bool g_sok = false;
struct StreamInit {
    StreamInit() {
        bool ok = (cudaStreamCreateWithFlags(&g_s1, cudaStreamNonBlocking) == cudaSuccess);
        for (int i = 0; i < 5 && ok; i++)
            ok = (cudaEventCreateWithFlags(&g_ev[i], cudaEventDisableTiming) == cudaSuccess);
        g_sok = ok;
    }
};
static StreamInit g_si;

#define SMEM_NI4 (NS * 16384)    // 80 KB, 2 CTA/SM
#define SMEM_NI8 (NS * 24576)    // 120 KB, 1 CTA/SM

// ---------------- host launch ----------------
static inline void conv(const float* s, __half* d, long long n, cudaStream_t st) {
    int n4 = (int)(n / 4);
    f2h_kernel<<<(n4 + 255) / 256, 256, 0, st>>>((const float4*)s, (uint2*)d, n4);
}

extern "C" void kernel_launch(void* const* d_in, const int* in_sizes, int n_in,
                              void* d_out, int out_size) {
    const float* hidden    = (const float*)d_in[0];
    const float* w_q_down  = (const float*)d_in[3];
    const float* q_norm_w  = (const float*)d_in[4];
    const float* w_q_up    = (const float*)d_in[5];
    const float* w_kv_down = (const float*)d_in[6];
    const float* kv_norm_w = (const float*)d_in[7];
    const float* w_kv_up   = (const float*)d_in[8];
    const float* w_out     = (const float*)d_in[9];
    float* outp = (float*)d_out;

    void* p;
    __half *hid16, *wqd, *wqup, *wkvd, *wkvup, *wout;
    __half *qtmp, *qbig, *c, *kv, *Q, *Kk, *Vt, *ctx, *attn16;
    float* attn_fb;
    cudaGetSymbolAddress(&p, g_hidden16); hid16 = (__half*)p;
    cudaGetSymbolAddress(&p, g_wqd16);    wqd   = (__half*)p;
    cudaGetSymbolAddress(&p, g_wqup16);   wqup  = (__half*)p;
    cudaGetSymbolAddress(&p, g_wkvd16);   wkvd  = (__half*)p;
    cudaGetSymbolAddress(&p, g_wkvup16);  wkvup = (__half*)p;
    cudaGetSymbolAddress(&p, g_wout16);   wout  = (__half*)p;
    cudaGetSymbolAddress(&p, g_qtmp16);   qtmp  = (__half*)p;
    cudaGetSymbolAddress(&p, g_qbig16);   qbig  = (__half*)p;
    cudaGetSymbolAddress(&p, g_c16);      c     = (__half*)p;
    cudaGetSymbolAddress(&p, g_kv16);     kv    = (__half*)p;
    cudaGetSymbolAddress(&p, g_Q16);      Q     = (__half*)p;
    cudaGetSymbolAddress(&p, g_K16);      Kk    = (__half*)p;
    cudaGetSymbolAddress(&p, g_Vt16);     Vt    = (__half*)p;
    cudaGetSymbolAddress(&p, g_ctx16);    ctx   = (__half*)p;
    cudaGetSymbolAddress(&p, g_attn16);   attn16= (__half*)p;
    cudaGetSymbolAddress(&p, g_attn_fb);  attn_fb = (float*)p;

    const long long OUT_ELEMS  = (long long)ROWS * HID;
    const long long ATTN_ELEMS = (long long)BATCH * NH * SEQ * SEQ;
    float* attn = ((long long)out_size >= OUT_ELEMS + ATTN_ELEMS) ? (outp + OUT_ELEMS)
                                                                  : attn_fb;

    static int inited = 0;
    if (!inited) {
        cudaFuncSetAttribute((const void*)gemm_h16<4,2>,
                             cudaFuncAttributeMaxDynamicSharedMemorySize, SMEM_NI4);
        cudaFuncSetAttribute((const void*)gemm_h16<8,1>,
                             cudaFuncAttributeMaxDynamicSharedMemorySize, SMEM_NI8);
        inited = 1;
    }
    dim3 thr(256);
    cudaStream_t s0 = 0;
    cudaStream_t s1 = g_sok ? g_s1 : (cudaStream_t)0;
    bool fk = g_sok;

    // fork s1 from capture stream
    if (fk) { cudaEventRecord(g_ev[0], s0); cudaStreamWaitEvent(s1, g_ev[0], 0); }

    // launches 0-2 (s0): convs feeding the merged down-proj
    conv(hidden,    hid16, (long long)ROWS * HID, s0);
    conv(w_q_down,  wqd,   (long long)1536 * HID, s0);
    conv(w_kv_down, wkvd,  (long long)576 * HID, s0);

    // launches 3-4 (s1): up-proj weight convs, overlapping s0's GEMM
    conv(w_q_up,  wqup,  (long long)3072 * 1536, s1);
    if (fk) cudaEventRecord(g_ev[1], s1);                 // wqup ready
    conv(w_kv_up, wkvup, (long long)4096 * 512, s1);

    // launch 5 (s0): merged down-proj  <- ncu -s 5 -c 1 target
    gemm_h16<4,2><<<dim3(17, ROWS/128, 1), thr, SMEM_NI4, s0>>>(
        hid16, wqd, qtmp, ROWS, 1536, HID, HID, HID, 1536,
        1, 0, 0, 0, 0, 0, 0, 1.0f, 0, 1,
        wkvd, c, 1536, 576, 576);
    if (fk) cudaEventRecord(g_ev[2], s0);                 // down-proj done

    // s1: zero the attn fp32 tail early (overlaps compute-bound GEMM phase)
    zero_tail<<<BATCH*NH*SEQ, 256, 0, s1>>>(attn);
    conv(w_out, wout, (long long)HID * HID, s1);

    rmsnorm16<<<ROWS, 256, 0, s0>>>(qtmp, q_norm_w, 1536, 1536);

    // s1 chain: rms(c) -> kv_up (NI=8) -> vtrans
    if (fk) cudaStreamWaitEvent(s1, g_ev[2], 0);
    rmsnorm16<<<ROWS, 256, 0, s1>>>(c, kv_norm_w, 512, 576);
    gemm_h16<8,1><<<dim3(4096/256, ROWS/128, 1), thr, SMEM_NI8, s1>>>(
        c, wkvup, kv, ROWS, 4096, 512, 576, 512, 4096,
        1, 0, 0, 0, 0, 0, 0, 1.0f, 0, 1,
        (const __half*)0, (void*)0, 0, 0, 0);
    if (fk) cudaEventRecord(g_ev[3], s1);                 // kv ready
    vtrans<<<dim3(SEQ/64, DV/32, BATCH*NH), thr, 0, s1>>>(kv, Vt);
    if (fk) cudaEventRecord(g_ev[4], s1);                 // Vt ready (joins all s1)

    // s0 chain: q_up (NI=8) -> rope -> scores (NI=8) -> softmax
    if (fk) cudaStreamWaitEvent(s0, g_ev[1], 0);
    gemm_h16<8,1><<<dim3(3072/256, ROWS/128, 1), thr, SMEM_NI8, s0>>>(
        qtmp, wqup, qbig, ROWS, 3072, 1536, 1536, 1536, 3072,
        1, 0, 0, 0, 0, 0, 0, 1.0f, 0, 1,
        (const __half*)0, (void*)0, 0, 0, 0);

    if (fk) cudaStreamWaitEvent(s0, g_ev[3], 0);
    rope_pack16<<<ROWS, 256, 0, s0>>>(qbig, c, kv, Q, Kk);

    // scores = Q K^T / sqrt(192); 256-wide tiles, epilogue clamps masked cols
    float alpha = rsqrtf((float)DQK);
    gemm_h16<8,1><<<dim3(SEQ/256, SEQ/128, BATCH*NH), thr, SMEM_NI8, s0>>>(
        Q, Kk, attn, SEQ, SEQ, DQK, DQK, DQK, SEQ,
        1, (long long)SEQ*DQK, 0,
        (long long)SEQ*DQK, 0,
        (long long)SEQ*SEQ, 0,
        alpha, 1, 0,
        (const __half*)0, (void*)0, 0, 0, 0);

    softmax_causal<<<BATCH*NH*SEQ, 256, 0, s0>>>(attn, attn16);

    // join s1, then attn@V (NI=4) and out-proj (NI=8)
    if (fk) cudaStreamWaitEvent(s0, g_ev[4], 0);
    gemm_h16<4,2><<<dim3(1, SEQ/128, BATCH*NH), thr, SMEM_NI4, s0>>>(
        attn16, Vt, ctx, SEQ, DV, SEQ, SEQ, SEQ, NH*DV,
        NH,
        (long long)NH*SEQ*SEQ, (long long)SEQ*SEQ,
        (long long)NH*DV*SEQ,  (long long)DV*SEQ,
        (long long)SEQ*NH*DV,  (long long)DV,
        1.0f, 2, 1,
        (const __half*)0, (void*)0, 0, 0, 0);

    gemm_h16<8,1><<<dim3(HID/256, ROWS/128, 1), thr, SMEM_NI8, s0>>>(
        ctx, wout, outp, ROWS, HID, NH*DV, NH*DV, NH*DV, HID,
        1, 0, 0, 0, 0, 0, 0, 1.0f, 0, 0,
        (const __half*)0, (void*)0, 0, 0, 0);
}

// round 16
// speedup vs baseline: 1.0684x; 1.0684x over previous
#include <cuda_runtime.h>
#include <cuda_fp16.h>
#include <math.h>
#include <stdint.h>

#define BATCH 2
#define SEQ   2048
#define HID   2048
#define NH    16
#define DNOPE 128
#define DROPE 64
#define DV    128
#define DQK   192
#define LORA  512
#define ROWS  (BATCH*SEQ)   // 4096
#define NS    5             // cp.async pipeline stages (single-sync design)

// ---------------- scratch (static device memory; no allocations) ----------------
__device__ __half g_hidden16[(size_t)ROWS*HID];
__device__ __half g_wqd16 [(size_t)1536*HID];
__device__ __half g_wqup16[(size_t)3072*1536];
__device__ __half g_wkvd16[(size_t)576*HID];
__device__ __half g_wkvup16[(size_t)4096*512];
__device__ __half g_wout16[(size_t)HID*HID];
__device__ __half g_qtmp16[(size_t)ROWS*1536];
__device__ __half g_qbig16[(size_t)ROWS*3072];
__device__ __half g_c16   [(size_t)ROWS*576];
__device__ __half g_kv16  [(size_t)ROWS*4096];
__device__ __half g_Q16   [(size_t)BATCH*NH*SEQ*DQK];
__device__ __half g_K16   [(size_t)BATCH*NH*SEQ*DQK];
__device__ __half g_Vt16  [(size_t)BATCH*NH*DV*SEQ];   // V transposed per (b,h)
__device__ __half g_ctx16 [(size_t)ROWS*NH*DV];
__device__ __half g_attn16[(size_t)BATCH*NH*SEQ*SEQ];  // fp16 attn for attn@V
__device__ float  g_attn_fb[(size_t)BATCH*NH*SEQ*SEQ]; // fallback fp32 attn

__device__ __forceinline__ uint32_t smem_u32(const void* p) {
    uint32_t a;
    asm("{ .reg .u64 t; cvta.to.shared.u64 t, %1; cvt.u32.u64 %0, t; }" : "=r"(a) : "l"(p));
    return a;
}

#define MMA_F16(ac, ar, br)                                                       \
    asm volatile("mma.sync.aligned.m16n8k16.row.col.f32.f16.f16.f32 "             \
                 "{%0,%1,%2,%3}, {%4,%5,%6,%7}, {%8,%9}, {%0,%1,%2,%3};"          \
                 : "+f"((ac)[0]), "+f"((ac)[1]), "+f"((ac)[2]), "+f"((ac)[3])     \
                 : "r"((ar)[0]), "r"((ar)[1]), "r"((ar)[2]), "r"((ar)[3]),        \
                   "r"((br)[0]), "r"((br)[1]))

#define LDSM_X4(r0, r1, r2, r3, addr)                                             \
    asm volatile("ldmatrix.sync.aligned.m8n8.x4.shared.b16 {%0,%1,%2,%3}, [%4];"  \
                 : "=r"(r0), "=r"(r1), "=r"(r2), "=r"(r3) : "r"(addr))

// ---------------- fp32 -> fp16 conversion ----------------
__global__ __launch_bounds__(256) void f2h_kernel(
    const float4* __restrict__ src, uint2* __restrict__ dst, int n4)
{
    int i = blockIdx.x * blockDim.x + threadIdx.x;
    if (i < n4) {
        float4 v = src[i];
        __half2 a = __floats2half2_rn(v.x, v.y);
        __half2 b = __floats2half2_rn(v.z, v.w);
        dst[i] = make_uint2(*(uint32_t*)&a, *(uint32_t*)&b);
    }
}

// ---------------- zero the masked fp32 attn tail (runs early, overlapped) -------
__global__ __launch_bounds__(256) void zero_tail(float* __restrict__ attn)
{
    long long r = blockIdx.x;
    int q = (int)(r % SEQ);
    int len16 = ((q + 1) + 127) & ~127;
    float4* row = (float4*)(attn + r * SEQ);
    float4 z4 = make_float4(0.f, 0.f, 0.f, 0.f);
    for (int i = (len16 >> 2) + threadIdx.x; i < SEQ / 4; i += 256)
        row[i] = z4;
}

// ---------------- fp16 mma.sync NT GEMM: cp.async.cg(16B) + ldmatrix.x4 ---------
// C[m,n] = alpha * sum_k A[m,k]*B[n,k] ; fp16 gmem, fp32 accumulate.
// CTA 128x128, BK=32, 8 warps (warp 64x32), 2 CTAs/SM, 5-stage single-sync pipe.
// (R13 lesson: 2 CTAs/SM is load-bearing — do not trade for wider tiles.)
// SMEM: row = 32 halves (64B) = 4 x 16B units, unit swizzle u^((row>>1)&3).
// mode: 0 dense, 1 causal tile-skip, 2 causal K-truncation (heavy-first order).
// Merged-output: tiles with n0 >= Nsplit switch to B2/C2/N2/ldc2.
#define GSMEM_BYTES (NS * 16384)

__global__ __launch_bounds__(256, 2) void gemm_h16(
    const __half* __restrict__ A, const __half* __restrict__ B, void* __restrict__ Cv,
    int M, int N, int K, int lda, int ldb, int ldc,
    int zdiv, long long sA1, long long sA2,
    long long sB1, long long sB2, long long sC1, long long sC2,
    float alpha, int mode, int outhalf,
    const __half* __restrict__ B2, void* __restrict__ C2,
    int Nsplit, int N2, int ldc2)
{
    int z  = blockIdx.z;
    int my = (mode == 2) ? (gridDim.y - 1 - blockIdx.y) : blockIdx.y;  // heavy-first
    int m0 = my * 128;
    int n0 = blockIdx.x * 128;
    if (mode == 1 && n0 > m0) return;   // masked tile: tail zeroed by zero_tail

    const __half* Ab = A + (long long)(z / zdiv) * sA1 + (long long)(z % zdiv) * sA2;
    const __half* Bb = B + (long long)(z / zdiv) * sB1 + (long long)(z % zdiv) * sB2;
    long long coff = (long long)(z / zdiv) * sC1 + (long long)(z % zdiv) * sC2;

    if (Nsplit > 0 && n0 >= Nsplit) {   // merged second output region
        Bb = B2; n0 -= Nsplit; N = N2; Cv = C2; ldc = ldc2; coff = 0;
    }

    extern __shared__ uint32_t sm[];
    uint32_t smb = smem_u32(sm);

    int t    = threadIdx.x;
    int lane = t & 31;
    int wid  = t >> 5;
    int g    = lane >> 2;
    int t4   = lane & 3;
    int wm   = wid >> 2;        // 0..1
    int wn   = wid & 3;         // 0..3

    int kEnd = K;
    if (mode == 2) { int ke = m0 + 128; kEnd = (ke < K) ? ke : K; }
    int nk = kEnd >> 5;

    float acc[4][4][4];
    #pragma unroll
    for (int mi = 0; mi < 4; mi++)
        #pragma unroll
        for (int ni = 0; ni < 4; ni++)
            #pragma unroll
            for (int r = 0; r < 4; r++) acc[mi][ni][r] = 0.0f;

    // ---- staging geometry: thread t covers 16B unit (row = t>>2 + 64*i, u = t&3)
    int urow = t >> 2;            // 0..63
    int uu   = t & 3;
    int sxu  = uu ^ ((urow >> 1) & 3);   // swizzled unit (invariant under row+=64)

    auto issue = [&](int kt, int st) {
        int k0 = kt << 5;
        uint32_t sA = smb + st * 16384;
        uint32_t sB = sA + 8192;
        #pragma unroll
        for (int i = 0; i < 2; i++) {
            int row = urow + i * 64;
            uint32_t dst = (uint32_t)(row * 64 + (sxu << 4));
            const __half* ga = Ab + (size_t)(m0 + row) * lda + k0 + uu * 8;
            asm volatile("cp.async.cg.shared.global [%0], [%1], 16;"
                         :: "r"(sA + dst), "l"(ga));
            int brow = n0 + row;
            const __half* gb = Bb + (size_t)(brow < N ? brow : 0) * ldb + k0 + uu * 8;
            int ssz = (brow < N) ? 16 : 0;
            asm volatile("cp.async.cg.shared.global [%0], [%1], 16, %2;"
                         :: "r"(sB + dst), "l"(gb), "r"(ssz));
        }
    };

    // ---- ldmatrix per-lane address components
    int m_idx = lane >> 3;        // matrix index 0..3
    int rin   = lane & 7;
    int arow0 = wm * 64 + rin + (m_idx & 1) * 8;
    int aun   = m_idx >> 1;                   // 0=klo,1=khi
    int axs   = (arow0 >> 1) & 3;
    uint32_t aoffb = (uint32_t)(arow0 * 64);
    int brow0 = wn * 32 + rin + (m_idx >> 1) * 8;
    int bun   = m_idx & 1;
    int bxs   = (brow0 >> 1) & 3;
    uint32_t boffb = (uint32_t)(brow0 * 64);

    auto mma_chunk = [&](int st) {
        uint32_t sA = smb + st * 16384;
        uint32_t sB = sA + 8192;
        #pragma unroll
        for (int ks = 0; ks < 2; ks++) {
            uint32_t af[4][4], bf[4][2];
            uint32_t au = (uint32_t)(((2 * ks + aun) ^ axs) << 4);
            uint32_t bu = (uint32_t)(((2 * ks + bun) ^ bxs) << 4);
            #pragma unroll
            for (int mi = 0; mi < 4; mi++)
                LDSM_X4(af[mi][0], af[mi][1], af[mi][2], af[mi][3],
                        sA + aoffb + (uint32_t)(mi * 1024) + au);
            #pragma unroll
            for (int p = 0; p < 2; p++)
                LDSM_X4(bf[2*p][0], bf[2*p][1], bf[2*p+1][0], bf[2*p+1][1],
                        sB + boffb + (uint32_t)(p * 1024) + bu);
            #pragma unroll
            for (int mi = 0; mi < 4; mi++)
                #pragma unroll
                for (int ni = 0; ni < 4; ni++)
                    MMA_F16(acc[mi][ni], af[mi], bf[ni]);
        }
    };

    // prologue
    #pragma unroll
    for (int s = 0; s < NS - 1; s++) {
        if (s < nk) issue(s, s);
        asm volatile("cp.async.commit_group;" ::: "memory");
    }

    int st = 0, stw = NS - 1;
    for (int kt = 0; kt < nk; kt++) {
        asm volatile("cp.async.wait_group %0;" :: "n"(NS - 2) : "memory");
        __syncthreads();
        mma_chunk(st);
        int nxt = kt + NS - 1;
        if (nxt < nk) issue(nxt, stw);
        asm volatile("cp.async.commit_group;" ::: "memory");
        if (++st == NS) st = 0;
        if (++stw == NS) stw = 0;
    }

    // epilogue
    #pragma unroll
    for (int mi = 0; mi < 4; mi++) {
        int row = m0 + wm * 64 + mi * 16 + g;
        #pragma unroll
        for (int ni = 0; ni < 4; ni++) {
            int col = n0 + wn * 32 + ni * 8 + 2 * t4;
            if (col < N) {
                if (outhalf) {
                    __half* Cb = (__half*)Cv + coff;
                    __half2 h0 = __floats2half2_rn(alpha * acc[mi][ni][0], alpha * acc[mi][ni][1]);
                    __half2 h1 = __floats2half2_rn(alpha * acc[mi][ni][2], alpha * acc[mi][ni][3]);
                    *(__half2*)(Cb + (size_t)row * ldc + col)       = h0;
                    *(__half2*)(Cb + (size_t)(row + 8) * ldc + col) = h1;
                } else {
                    float* Cb = (float*)Cv + coff;
                    float2 v0 = make_float2(alpha * acc[mi][ni][0], alpha * acc[mi][ni][1]);
                    float2 v1 = make_float2(alpha * acc[mi][ni][2], alpha * acc[mi][ni][3]);
                    *(float2*)(Cb + (size_t)row * ldc + col)       = v0;
                    *(float2*)(Cb + (size_t)(row + 8) * ldc + col) = v1;
                }
            }
        }
    }
}

// ---------------- block reductions ----------------
__device__ __forceinline__ float blockReduceSum(float v) {
    __shared__ float sh[32];
    int lane = threadIdx.x & 31, w = threadIdx.x >> 5;
    #pragma unroll
    for (int o = 16; o > 0; o >>= 1) v += __shfl_xor_sync(0xffffffffu, v, o);
    __syncthreads();
    if (lane == 0) sh[w] = v;
    __syncthreads();
    int nw = (blockDim.x + 31) >> 5;
    float r = (threadIdx.x < nw) ? sh[threadIdx.x] : 0.0f;
    if (w == 0) {
        #pragma unroll
        for (int o = 16; o > 0; o >>= 1) r += __shfl_xor_sync(0xffffffffu, r, o);
        if (lane == 0) sh[0] = r;
    }
    __syncthreads();
    return sh[0];
}
__device__ __forceinline__ float blockReduceMax(float v) {
    __shared__ float sh[32];
    int lane = threadIdx.x & 31, w = threadIdx.x >> 5;
    #pragma unroll
    for (int o = 16; o > 0; o >>= 1) v = fmaxf(v, __shfl_xor_sync(0xffffffffu, v, o));
    __syncthreads();
    if (lane == 0) sh[w] = v;
    __syncthreads();
    int nw = (blockDim.x + 31) >> 5;
    float r = (threadIdx.x < nw) ? sh[threadIdx.x] : -INFINITY;
    if (w == 0) {
        #pragma unroll
        for (int o = 16; o > 0; o >>= 1) r = fmaxf(r, __shfl_xor_sync(0xffffffffu, r, o));
        if (lane == 0) sh[0] = r;
    }
    __syncthreads();
    return sh[0];
}

// ---------------- RMSNorm fp16 (in place, vectorized 4-half access) -------------
__global__ __launch_bounds__(256) void rmsnorm16(
    __half* __restrict__ x, const float* __restrict__ w, int W, int stride)
{
    __half* row = x + (long long)blockIdx.x * stride;
    uint2* row4 = (uint2*)row;
    const float4* w4 = (const float4*)w;
    int n4 = W >> 2;

    float ss = 0.0f;
    for (int i = threadIdx.x; i < n4; i += blockDim.x) {
        uint2 u = row4[i];
        __half2 a = *(__half2*)&u.x;
        __half2 b = *(__half2*)&u.y;
        float2 fa = __half22float2(a);
        float2 fb = __half22float2(b);
        ss += fa.x * fa.x + fa.y * fa.y + fb.x * fb.x + fb.y * fb.y;
    }
    ss = blockReduceSum(ss);
    float sc = rsqrtf(ss / (float)W + 1e-6f);

    for (int i = threadIdx.x; i < n4; i += blockDim.x) {
        uint2 u = row4[i];
        float4 wv = w4[i];
        __half2 a = *(__half2*)&u.x;
        __half2 b = *(__half2*)&u.y;
        float2 fa = __half22float2(a);
        float2 fb = __half22float2(b);
        __half2 oa = __floats2half2_rn(fa.x * sc * wv.x, fa.y * sc * wv.y);
        __half2 ob = __floats2half2_rn(fb.x * sc * wv.z, fb.y * sc * wv.w);
        row4[i] = make_uint2(*(uint32_t*)&oa, *(uint32_t*)&ob);
    }
}

// ---------------- RoPE + pack fp16 (Q, K only) ----------------
__global__ __launch_bounds__(256) void rope_pack16(
    const __half* __restrict__ q,   // [ROWS,3072]
    const __half* __restrict__ c,   // [ROWS,576]
    const __half* __restrict__ kv,  // [ROWS,4096]
    __half* __restrict__ Qo,        // [B,NH,S,192]
    __half* __restrict__ Ko)        // [B,NH,S,192]
{
    int row = blockIdx.x;
    int b = row / SEQ, s = row % SEQ;
    int t = threadIdx.x;

    __shared__ float cs[32], sn[32];
    __shared__ __half kr[64];
    if (t < 32) {
        float f = exp10f(-(float)t / 8.0f);   // 10000^(-t/32)
        float ang = (float)s * f;
        sincosf(ang, &sn[t], &cs[t]);
    }
    __syncthreads();
    if (t < 64) {
        const __half* kx = c + (long long)row * 576 + 512;
        int j = t; float v;
        if (j < 32) v = __half2float(kx[2*j]) * cs[j] - __half2float(kx[2*j+1]) * sn[j];
        else { int i = j - 32; v = __half2float(kx[2*i+1]) * cs[i] + __half2float(kx[2*i]) * sn[i]; }
        kr[j] = __float2half(v);
    }
    __syncthreads();

    const __half* qrow = q + (long long)row * 3072;
    for (int idx = t; idx < NH * DQK; idx += 256) {
        int h = idx / DQK, d = idx % DQK;
        __half v;
        if (d < DNOPE) v = qrow[h * DQK + d];
        else {
            int j = d - DNOPE;
            const __half* qx = qrow + h * DQK + DNOPE;
            float vv;
            if (j < 32) vv = __half2float(qx[2*j]) * cs[j] - __half2float(qx[2*j+1]) * sn[j];
            else { int i = j - 32; vv = __half2float(qx[2*i+1]) * cs[i] + __half2float(qx[2*i]) * sn[i]; }
            v = __float2half(vv);
        }
        Qo[((long long)(b * NH + h) * SEQ + s) * DQK + d] = v;
    }

    const __half* kvrow = kv + (long long)row * 4096;
    for (int idx = t; idx < NH * DQK; idx += 256) {
        int h = idx / DQK, d = idx % DQK;
        __half v = (d < DNOPE) ? kvrow[h * 256 + d] : kr[d - DNOPE];
        Ko[((long long)(b * NH + h) * SEQ + s) * DQK + d] = v;
    }
}

// ---------------- V transpose: kv16[b,s,h,256](+128) -> Vt[bh, d, s] ------------
__global__ __launch_bounds__(256) void vtrans(
    const __half* __restrict__ kv, __half* __restrict__ Vt)
{
    __shared__ __half tile[64][33];
    int s0 = blockIdx.x * 64;
    int d0 = blockIdx.y * 32;
    int z  = blockIdx.z;           // b*NH + h
    int b = z / NH, h = z % NH;
    int tx = threadIdx.x & 31;
    int ty = threadIdx.x >> 5;     // 0..7
    const __half* src = kv + (size_t)b * SEQ * 4096 + h * 256 + 128 + d0;
    #pragma unroll
    for (int k = 0; k < 8; k++) {
        int row = ty * 8 + k;
        tile[row][tx] = src[(size_t)(s0 + row) * 4096 + tx];
    }
    __syncthreads();
    #pragma unroll
    for (int k = 0; k < 4; k++) {
        int d = ty + 8 * k;
        __half2 v = __halves2half2(tile[2 * tx][d], tile[2 * tx + 1][d]);
        *(__half2*)&Vt[((size_t)z * DV + d0 + d) * SEQ + s0 + 2 * tx] = v;
    }
}

// ---------------- causal softmax: fp32 writes trimmed to the diagonal block -----
// The fp32 tail [len16, SEQ) was zero-filled by zero_tail (early, overlapped).
__global__ __launch_bounds__(256) void softmax_causal(
    float* __restrict__ attn, __half* __restrict__ attn16)
{
    long long r = blockIdx.x;
    int q = (int)(r % SEQ);
    float4* row4   = (float4*)(attn + r * SEQ);
    uint2*  row16  = (uint2*)(attn16 + r * SEQ);
    int t = threadIdx.x;
    int len = q + 1;
    int len16 = (len + 127) & ~127;

    float4 v[2];
    float mx = -INFINITY;
    #pragma unroll
    for (int it = 0; it < 2; it++) {
        int i4 = t + it * 256;
        int base = i4 * 4;
        float4 x = make_float4(-INFINITY, -INFINITY, -INFINITY, -INFINITY);
        if (base < len) {
            x = row4[i4];
            if (base + 1 >= len) x.y = -INFINITY;
            if (base + 2 >= len) x.z = -INFINITY;
            if (base + 3 >= len) x.w = -INFINITY;
        }
        v[it] = x;
        mx = fmaxf(mx, fmaxf(fmaxf(x.x, x.y), fmaxf(x.z, x.w)));
    }
    mx = blockReduceMax(mx);

    float sum = 0.0f;
    #pragma unroll
    for (int it = 0; it < 2; it++) {
        float4 x = v[it];
        x.x = (x.x == -INFINITY) ? 0.0f : __expf(x.x - mx);
        x.y = (x.y == -INFINITY) ? 0.0f : __expf(x.y - mx);
        x.z = (x.z == -INFINITY) ? 0.0f : __expf(x.z - mx);
        x.w = (x.w == -INFINITY) ? 0.0f : __expf(x.w - mx);
        v[it] = x;
        sum += x.x + x.y + x.z + x.w;
    }
    sum = blockReduceSum(sum);
    float inv = 1.0f / sum;

    #pragma unroll
    for (int it = 0; it < 2; it++) {
        int i4 = t + it * 256;
        int base = i4 * 4;
        if (base < len16) {
            float4 x = v[it];
            x.x *= inv; x.y *= inv; x.z *= inv; x.w *= inv;
            row4[i4] = x;
            __half2 a = __floats2half2_rn(x.x, x.y);
            __half2 b = __floats2half2_rn(x.z, x.w);
            row16[i4] = make_uint2(*(uint32_t*)&a, *(uint32_t*)&b);
        }
    }
}

// ---------------- streams/events for graph-capture fork/join --------------------
static cudaStream_t g_s1 = 0;
static cudaEvent_t  g_ev[5];
static bool g_sok = false;
struct StreamInit {
    StreamInit() {
        bool ok = (cudaStreamCreateWithFlags(&g_s1, cudaStreamNonBlocking) == cudaSuccess);
        for (int i = 0; i < 5 && ok; i++)
            ok = (cudaEventCreateWithFlags(&g_ev[i], cudaEventDisableTiming) == cudaSuccess);
        g_sok = ok;
    }
};
static StreamInit g_si;

// ---------------- host launch ----------------
static inline void conv(const float* s, __half* d, long long n, cudaStream_t st) {
    int n4 = (int)(n / 4);
    f2h_kernel<<<(n4 + 255) / 256, 256, 0, st>>>((const float4*)s, (uint2*)d, n4);
}

extern "C" void kernel_launch(void* const* d_in, const int* in_sizes, int n_in,
                              void* d_out, int out_size) {
    const float* hidden    = (const float*)d_in[0];
    const float* w_q_down  = (const float*)d_in[3];
    const float* q_norm_w  = (const float*)d_in[4];
    const float* w_q_up    = (const float*)d_in[5];
    const float* w_kv_down = (const float*)d_in[6];
    const float* kv_norm_w = (const float*)d_in[7];
    const float* w_kv_up   = (const float*)d_in[8];
    const float* w_out     = (const float*)d_in[9];
    float* outp = (float*)d_out;

    void* p;
    __half *hid16, *wqd, *wqup, *wkvd, *wkvup, *wout;
    __half *qtmp, *qbig, *c, *kv, *Q, *Kk, *Vt, *ctx, *attn16;
    float* attn_fb;
    cudaGetSymbolAddress(&p, g_hidden16); hid16 = (__half*)p;
    cudaGetSymbolAddress(&p, g_wqd16);    wqd   = (__half*)p;
    cudaGetSymbolAddress(&p, g_wqup16);   wqup  = (__half*)p;
    cudaGetSymbolAddress(&p, g_wkvd16);   wkvd  = (__half*)p;
    cudaGetSymbolAddress(&p, g_wkvup16);  wkvup = (__half*)p;
    cudaGetSymbolAddress(&p, g_wout16);   wout  = (__half*)p;
    cudaGetSymbolAddress(&p, g_qtmp16);   qtmp  = (__half*)p;
    cudaGetSymbolAddress(&p, g_qbig16);   qbig  = (__half*)p;
    cudaGetSymbolAddress(&p, g_c16);      c     = (__half*)p;
    cudaGetSymbolAddress(&p, g_kv16);     kv    = (__half*)p;
    cudaGetSymbolAddress(&p, g_Q16);      Q     = (__half*)p;
    cudaGetSymbolAddress(&p, g_K16);      Kk    = (__half*)p;
    cudaGetSymbolAddress(&p, g_Vt16);     Vt    = (__half*)p;
    cudaGetSymbolAddress(&p, g_ctx16);    ctx   = (__half*)p;
    cudaGetSymbolAddress(&p, g_attn16);   attn16= (__half*)p;
    cudaGetSymbolAddress(&p, g_attn_fb);  attn_fb = (float*)p;

    const long long OUT_ELEMS  = (long long)ROWS * HID;
    const long long ATTN_ELEMS = (long long)BATCH * NH * SEQ * SEQ;
    float* attn = ((long long)out_size >= OUT_ELEMS + ATTN_ELEMS) ? (outp + OUT_ELEMS)
                                                                  : attn_fb;

    static int inited = 0;
    if (!inited) {
        cudaFuncSetAttribute(gemm_h16, cudaFuncAttributeMaxDynamicSharedMemorySize, GSMEM_BYTES);
        inited = 1;
    }
    dim3 thr(256);
    cudaStream_t s0 = 0;
    cudaStream_t s1 = g_sok ? g_s1 : (cudaStream_t)0;
    bool fk = g_sok;

    // fork s1 from capture stream
    if (fk) { cudaEventRecord(g_ev[0], s0); cudaStreamWaitEvent(s1, g_ev[0], 0); }

    // launches 0-2 (s0): convs feeding the merged down-proj
    conv(hidden,    hid16, (long long)ROWS * HID, s0);
    conv(w_q_down,  wqd,   (long long)1536 * HID, s0);
    conv(w_kv_down, wkvd,  (long long)576 * HID, s0);

    // launches 3-4 (s1): up-proj weight convs, overlapping s0's GEMM
    conv(w_q_up,  wqup,  (long long)3072 * 1536, s1);
    if (fk) cudaEventRecord(g_ev[1], s1);                 // wqup ready
    conv(w_kv_up, wkvup, (long long)4096 * 512, s1);

    // launch 5 (s0): merged down-proj  <- ncu -s 5 -c 1 target
    gemm_h16<<<dim3(17, ROWS/128, 1), thr, GSMEM_BYTES, s0>>>(
        hid16, wqd, qtmp, ROWS, 1536, HID, HID, HID, 1536,
        1, 0, 0, 0, 0, 0, 0, 1.0f, 0, 1,
        wkvd, c, 1536, 576, 576);
    if (fk) cudaEventRecord(g_ev[2], s0);                 // down-proj done

    // s1: zero the attn fp32 tail early (overlaps compute-bound GEMM phase)
    zero_tail<<<BATCH*NH*SEQ, 256, 0, s1>>>(attn);
    conv(w_out, wout, (long long)HID * HID, s1);

    rmsnorm16<<<ROWS, 256, 0, s0>>>(qtmp, q_norm_w, 1536, 1536);

    // s1 chain: rms(c) -> kv_up -> vtrans
    if (fk) cudaStreamWaitEvent(s1, g_ev[2], 0);
    rmsnorm16<<<ROWS, 256, 0, s1>>>(c, kv_norm_w, 512, 576);
    gemm_h16<<<dim3(4096/128, ROWS/128, 1), thr, GSMEM_BYTES, s1>>>(
        c, wkvup, kv, ROWS, 4096, 512, 576, 512, 4096,
        1, 0, 0, 0, 0, 0, 0, 1.0f, 0, 1,
        (const __half*)0, (void*)0, 0, 0, 0);
    if (fk) cudaEventRecord(g_ev[3], s1);                 // kv ready
    vtrans<<<dim3(SEQ/64, DV/32, BATCH*NH), thr, 0, s1>>>(kv, Vt);
    if (fk) cudaEventRecord(g_ev[4], s1);                 // Vt ready (joins all s1)

    // s0 chain: q_up (needs wqup) -> rope (needs kv) -> scores -> softmax
    if (fk) cudaStreamWaitEvent(s0, g_ev[1], 0);
    gemm_h16<<<dim3(3072/128, ROWS/128, 1), thr, GSMEM_BYTES, s0>>>(
        qtmp, wqup, qbig, ROWS, 3072, 1536, 1536, 1536, 3072,
        1, 0, 0, 0, 0, 0, 0, 1.0f, 0, 1,
        (const __half*)0, (void*)0, 0, 0, 0);

    if (fk) cudaStreamWaitEvent(s0, g_ev[3], 0);
    rope_pack16<<<ROWS, 256, 0, s0>>>(qbig, c, kv, Q, Kk);

    // scores = Q K^T / sqrt(192); masked tiles skipped (tail pre-zeroed)
    float alpha = rsqrtf((float)DQK);
    gemm_h16<<<dim3(SEQ/128, SEQ/128, BATCH*NH), thr, GSMEM_BYTES, s0>>>(
        Q, Kk, attn, SEQ, SEQ, DQK, DQK, DQK, SEQ,
        1, (long long)SEQ*DQK, 0,
        (long long)SEQ*DQK, 0,
        (long long)SEQ*SEQ, 0,
        alpha, 1, 0,
        (const __half*)0, (void*)0, 0, 0, 0);

    softmax_causal<<<BATCH*NH*SEQ, 256, 0, s0>>>(attn, attn16);

    // join s1, then attn@V and out-proj
    if (fk) cudaStreamWaitEvent(s0, g_ev[4], 0);
    gemm_h16<<<dim3(1, SEQ/128, BATCH*NH), thr, GSMEM_BYTES, s0>>>(
        attn16, Vt, ctx, SEQ, DV, SEQ, SEQ, SEQ, NH*DV,
        NH,
        (long long)NH*SEQ*SEQ, (long long)SEQ*SEQ,
        (long long)NH*DV*SEQ,  (long long)DV*SEQ,
        (long long)SEQ*NH*DV,  (long long)DV,
        1.0f, 2, 1,
        (const __half*)0, (void*)0, 0, 0, 0);

    gemm_h16<<<dim3(HID/128, ROWS/128, 1), thr, GSMEM_BYTES, s0>>>(
        ctx, wout, outp, ROWS, HID, NH*DV, NH*DV, NH*DV, HID,
        1, 0, 0, 0, 0, 0, 0, 1.0f, 0, 0,
        (const __half*)0, (void*)0, 0, 0, 0);
}